// round 1
// baseline (speedup 1.0000x reference)
#include <cuda_runtime.h>

// SpatialTransformer: per-batch 3D trilinear warp, faithful to
// transform()+interpn(linear, ij) including the clipped-corner weight quirk:
//   loc0c = clip(floor(loc), 0, max); loc1c = clip(loc0c+1, 0, max)
//   d1 = loc1c - loc  (weight for the FLOOR corner)
//   d0 = 1 - d1       (weight for the CEIL  corner)

#define Bn 2
#define Dn 160
#define Hn 160
#define Wn 160
// C = 2 (float2)

__global__ __launch_bounds__(256)
void st_warp_kernel(const float* __restrict__ vol,
                    const float* __restrict__ trf,
                    float* __restrict__ out)
{
    const int idx = blockIdx.x * blockDim.x + threadIdx.x;   // voxel index over B*D*H*W
    constexpr int NVOX = Bn * Dn * Hn * Wn;
    if (idx >= NVOX) return;

    int x = idx % Wn;
    int t = idx / Wn;
    int y = t % Hn;
    t /= Hn;
    int z = t % Dn;
    int b = t / Dn;

    // displacement (stride-3 layout)
    const float sz = __ldg(trf + 3 * idx + 0);
    const float sy = __ldg(trf + 3 * idx + 1);
    const float sx = __ldg(trf + 3 * idx + 2);

    const float lz = (float)z + sz;
    const float ly = (float)y + sy;
    const float lx = (float)x + sx;

    // floor corner, clipped; ceil = clip(floor_clipped + 1)
    float fz = floorf(lz), fy = floorf(ly), fx = floorf(lx);
    float z0f = fminf(fmaxf(fz, 0.0f), (float)(Dn - 1));
    float y0f = fminf(fmaxf(fy, 0.0f), (float)(Hn - 1));
    float x0f = fminf(fmaxf(fx, 0.0f), (float)(Wn - 1));
    float z1f = fminf(z0f + 1.0f, (float)(Dn - 1));
    float y1f = fminf(y0f + 1.0f, (float)(Hn - 1));
    float x1f = fminf(x0f + 1.0f, (float)(Wn - 1));

    // weights: d1 pairs with floor corner, d0 with ceil corner (reference quirk)
    const float dz1 = z1f - lz, dz0 = 1.0f - dz1;
    const float dy1 = y1f - ly, dy0 = 1.0f - dy1;
    const float dx1 = x1f - lx, dx0 = 1.0f - dx1;

    const int z0 = (int)z0f, z1 = (int)z1f;
    const int y0 = (int)y0f, y1 = (int)y1f;
    const int x0 = (int)x0f, x1 = (int)x1f;

    // vol as float2 (C=2 innermost). Linear index = ((b*D + z)*H + y)*W + x
    const float2* __restrict__ v = (const float2*)vol;
    const int base_b = b * (Dn * Hn * Wn);
    const int r00 = base_b + (z0 * Hn + y0) * Wn;   // z0,y0 row
    const int r01 = base_b + (z0 * Hn + y1) * Wn;   // z0,y1 row
    const int r10 = base_b + (z1 * Hn + y0) * Wn;   // z1,y0 row
    const int r11 = base_b + (z1 * Hn + y1) * Wn;   // z1,y1 row

    const float2 c000 = __ldg(&v[r00 + x0]);
    const float2 c001 = __ldg(&v[r00 + x1]);
    const float2 c010 = __ldg(&v[r01 + x0]);
    const float2 c011 = __ldg(&v[r01 + x1]);
    const float2 c100 = __ldg(&v[r10 + x0]);
    const float2 c101 = __ldg(&v[r10 + x1]);
    const float2 c110 = __ldg(&v[r11 + x0]);
    const float2 c111 = __ldg(&v[r11 + x1]);

    const float w000 = dz1 * dy1 * dx1;
    const float w001 = dz1 * dy1 * dx0;
    const float w010 = dz1 * dy0 * dx1;
    const float w011 = dz1 * dy0 * dx0;
    const float w100 = dz0 * dy1 * dx1;
    const float w101 = dz0 * dy1 * dx0;
    const float w110 = dz0 * dy0 * dx1;
    const float w111 = dz0 * dy0 * dx0;

    float2 o;
    o.x = w000 * c000.x + w001 * c001.x + w010 * c010.x + w011 * c011.x
        + w100 * c100.x + w101 * c101.x + w110 * c110.x + w111 * c111.x;
    o.y = w000 * c000.y + w001 * c001.y + w010 * c010.y + w011 * c011.y
        + w100 * c100.y + w101 * c101.y + w110 * c110.y + w111 * c111.y;

    ((float2*)out)[idx] = o;
}

extern "C" void kernel_launch(void* const* d_in, const int* in_sizes, int n_in,
                              void* d_out, int out_size)
{
    const float* vol = (const float*)d_in[0];
    const float* trf = (const float*)d_in[1];
    float* out = (float*)d_out;

    constexpr int NVOX = Bn * Dn * Hn * Wn;      // 8,192,000
    const int threads = 256;
    const int blocks = (NVOX + threads - 1) / threads;
    st_warp_kernel<<<blocks, threads>>>(vol, trf, out);
}